// round 1
// baseline (speedup 1.0000x reference)
#include <cuda_runtime.h>
#include <math.h>

// Problem dims (fixed by the reference)
#define M_ROWS 16384
#define K_DIM  4096
#define N_DIM  4096

// GEMM tiling
#define BM 128
#define BN 128
#define BK 32
#define PAD 4   // smem row padding (floats) -> 16B-aligned rows, reduced conflicts

// Scratch: per-row signed popcount accumulator s[b] = sum_j sign(h[b,j])*sign(W2[j]).
// Values are exact small integers in fp32, so float atomicAdd is order-independent
// and the result is deterministic.
__device__ float g_s[M_ROWS];

__global__ void zero_s_kernel() {
    int i = blockIdx.x * blockDim.x + threadIdx.x;
    if (i < M_ROWS) g_s[i] = 0.0f;
}

// Fused kernel: C_tile = X_tile @ sign(W1_tile)^T  (fp32 FFMA, exact +/-x products),
// then epilogue reduces sign(C) * sign(W2) over the N-tile into g_s via atomicAdd.
// h is never materialized in global memory.
__global__ __launch_bounds__(256, 2)
void gemm_sign_kernel(const float* __restrict__ X,
                      const float* __restrict__ W1,
                      const float* __restrict__ W2) {
    __shared__ float As[BK][BM + PAD];  // As[k][m], X tile transposed into smem
    __shared__ float Bs[BK][BN + PAD];  // Bs[k][n], sign(W1) tile transposed

    const int bm  = blockIdx.y * BM;
    const int bn  = blockIdx.x * BN;
    const int tid = threadIdx.x;       // 0..255
    const int tx  = tid & 15;          // 16 thread columns
    const int ty  = tid >> 4;          // 16 thread rows

    // Each thread owns an 8x8 micro-tile:
    //   rows: bm + ty*4 + r      (r=0..3)   and bm + 64 + ty*4 + (r-4)  (r=4..7)
    //   cols: bn + tx*4 + c      (c=0..3)   and bn + 64 + tx*4 + (c-4)  (c=4..7)
    float acc[8][8];
#pragma unroll
    for (int r = 0; r < 8; r++)
#pragma unroll
        for (int c = 0; c < 8; c++) acc[r][c] = 0.0f;

    for (int k0 = 0; k0 < K_DIM; k0 += BK) {
        // Cooperative load: 128 rows x 32 k-cols per tile, as 128x8 float4 loads.
        // 1024 float4 per tile, 256 threads -> 4 each. Coalesced along k.
#pragma unroll
        for (int i = 0; i < 4; i++) {
            int id  = tid + 256 * i;
            int row = id >> 3;        // 0..127
            int vc  = id & 7;         // float4 column 0..7
            int kk  = vc * 4;

            float4 a = *reinterpret_cast<const float4*>(
                &X[(size_t)(bm + row) * K_DIM + k0 + kk]);
            As[kk + 0][row] = a.x;
            As[kk + 1][row] = a.y;
            As[kk + 2][row] = a.z;
            As[kk + 3][row] = a.w;

            float4 b = *reinterpret_cast<const float4*>(
                &W1[(size_t)(bn + row) * K_DIM + k0 + kk]);
            Bs[kk + 0][row] = (b.x >= 0.0f) ? 1.0f : -1.0f;
            Bs[kk + 1][row] = (b.y >= 0.0f) ? 1.0f : -1.0f;
            Bs[kk + 2][row] = (b.z >= 0.0f) ? 1.0f : -1.0f;
            Bs[kk + 3][row] = (b.w >= 0.0f) ? 1.0f : -1.0f;
        }
        __syncthreads();

#pragma unroll
        for (int kk = 0; kk < BK; kk++) {
            // Vectorized smem reads; As row base is 16B aligned (PAD=4).
            float4 av0 = *reinterpret_cast<const float4*>(&As[kk][ty * 4]);
            float4 av1 = *reinterpret_cast<const float4*>(&As[kk][64 + ty * 4]);
            float4 bv0 = *reinterpret_cast<const float4*>(&Bs[kk][tx * 4]);
            float4 bv1 = *reinterpret_cast<const float4*>(&Bs[kk][64 + tx * 4]);
            float a[8] = {av0.x, av0.y, av0.z, av0.w, av1.x, av1.y, av1.z, av1.w};
            float b[8] = {bv0.x, bv0.y, bv0.z, bv0.w, bv1.x, bv1.y, bv1.z, bv1.w};
#pragma unroll
            for (int r = 0; r < 8; r++)
#pragma unroll
                for (int c = 0; c < 8; c++)
                    acc[r][c] = fmaf(a[r], b[c], acc[r][c]);
        }
        __syncthreads();
    }

    // Epilogue: p[r] = sum_c sign(acc[r][c]) * sign(W2[col(c)])
    // sign convention matches reference binarize: (v >= 0) -> +1.
    bool w2pos[8];
#pragma unroll
    for (int c = 0; c < 8; c++) {
        int col = bn + ((c < 4) ? (tx * 4 + c) : (64 + tx * 4 + (c - 4)));
        w2pos[c] = (W2[col] >= 0.0f);
    }

    float p[8];
#pragma unroll
    for (int r = 0; r < 8; r++) {
        float s = 0.0f;
#pragma unroll
        for (int c = 0; c < 8; c++) {
            bool hpos = (acc[r][c] >= 0.0f);
            s += (hpos == w2pos[c]) ? 1.0f : -1.0f;
        }
        p[r] = s;
    }

    // Reduce over the 16 tx-lanes (they share the same rows). Lanes 0..15 of a
    // warp have ty even, 16..31 ty odd, so width-16 shuffles reduce each group.
#pragma unroll
    for (int r = 0; r < 8; r++) {
#pragma unroll
        for (int off = 8; off >= 1; off >>= 1)
            p[r] += __shfl_down_sync(0xffffffffu, p[r], off, 16);
    }

    if (tx == 0) {
#pragma unroll
        for (int r = 0; r < 8; r++) {
            int row = bm + ((r < 4) ? (ty * 4 + r) : (64 + ty * 4 + (r - 4)));
            atomicAdd(&g_s[row], p[r]);
        }
    }
}

__global__ void finalize_kernel(float* __restrict__ out, int out_size) {
    int b = blockIdx.x * blockDim.x + threadIdx.x;
    if (b >= M_ROWS) return;
    float s = g_s[b];
    float o = 1.0f / (1.0f + expf(-s));        // sigmoid; saturates exactly to 0/1 for |s| large
    if (b < out_size) out[b] = o;
    int yi = M_ROWS + b;                        // y_hat = (out >= 0.5) <=> (s >= 0)
    if (yi < out_size) out[yi] = (s >= 0.0f) ? 1.0f : 0.0f;
}

extern "C" void kernel_launch(void* const* d_in, const int* in_sizes, int n_in,
                              void* d_out, int out_size) {
    const float* X  = (const float*)d_in[0];   // [16384, 4096]
    const float* W1 = (const float*)d_in[1];   // [4096, 4096]
    const float* W2 = (const float*)d_in[2];   // [1, 4096]
    float* out = (float*)d_out;

    zero_s_kernel<<<(M_ROWS + 255) / 256, 256>>>();

    dim3 grid(N_DIM / BN, M_ROWS / BM);        // (32, 128) = 4096 CTAs
    gemm_sign_kernel<<<grid, 256>>>(X, W1, W2);

    finalize_kernel<<<(M_ROWS + 255) / 256, 256>>>(out, out_size);
}